// round 15
// baseline (speedup 1.0000x reference)
#include <cuda_runtime.h>
#include <math.h>
#include <stdint.h>

#define NTOT 32768
#define QB   8192
#define NBATCH 4
#define EDG  524288
#define KNN  20

// ---------------- cp.async helpers ----------------
__device__ __forceinline__ void cp_async16(void* smem_dst, const void* gmem_src) {
    uint32_t d = (uint32_t)__cvta_generic_to_shared(smem_dst);
    asm volatile("cp.async.cg.shared.global [%0], [%1], 16;" :: "r"(d), "l"(gmem_src));
}
__device__ __forceinline__ void cp_async_commit() {
    asm volatile("cp.async.commit_group;");
}
__device__ __forceinline__ void cp_async_wait0() {
    asm volatile("cp.async.wait_group 0;");
}

// ---------------- packed f32x2 helpers (Blackwell, exact per-lane RN) ----------------
__device__ __forceinline__ uint64_t sub2(uint64_t a, uint64_t b) {
    uint64_t d;
    asm("sub.rn.f32x2 %0, %1, %2;" : "=l"(d) : "l"(a), "l"(b));
    return d;
}
__device__ __forceinline__ uint64_t fma2(uint64_t a, uint64_t b, uint64_t c) {
    uint64_t d;
    asm("fma.rn.f32x2 %0, %1, %2, %3;" : "=l"(d) : "l"(a), "l"(b), "l"(c));
    return d;
}
__device__ __forceinline__ void unpack2(uint64_t v, float& lo, float& hi) {
    asm("mov.b64 {%0, %1}, %2;" : "=f"(lo), "=f"(hi) : "l"(v));
}

// ---------------- scratch (static device globals; no allocation) ----------------
__device__ __align__(16) float g_f[NTOT * 128];    // pooled edge features
__device__ __align__(16) float g_m[NTOT * 128];    // ns-scaled messages
__device__ __align__(16) float g_agg[NTOT * 128];  // segment-sum result
__device__ __align__(16) float g_h1[NTOT * 64];
__device__ __align__(16) float g_h2[NTOT * 64];
__device__ float g_ns[NTOT];
__device__ float g_nd[NTOT];
// CSR over dst (edge ids ascending per node)
__device__ int g_degi[NTOT];
__device__ int g_base[NTOT + 1];
__device__ int g_cursor[NTOT];
__device__ int g_elist[EDG];

// ---------------- small utility kernels ----------------
__global__ void zero_f_kernel(float* __restrict__ p, int n) {
    int i = blockIdx.x * blockDim.x + threadIdx.x;
    if (i < n) p[i] = 0.f;
}
__global__ void zero_i_kernel(int* __restrict__ p, int n) {
    int i = blockIdx.x * blockDim.x + threadIdx.x;
    if (i < n) p[i] = 0;
}

__global__ void deg_kernel(const int* __restrict__ src, const int* __restrict__ dst,
                           float* __restrict__ dego, float* __restrict__ degi,
                           int* __restrict__ degi_i) {
    int e = blockIdx.x * blockDim.x + threadIdx.x;
    if (e < EDG) {
        atomicAdd(&dego[src[e]], 1.f);
        atomicAdd(&degi[dst[e]], 1.f);
        atomicAdd(&degi_i[dst[e]], 1);
    }
}

__global__ void norm_kernel(float* __restrict__ a, int n) {
    int i = blockIdx.x * blockDim.x + threadIdx.x;
    if (i < n) {
        float d = a[i];
        a[i] = (d > 0.f) ? (float)(1.0 / sqrt((double)fmaxf(d, 1.f))) : 0.f;
    }
}

// exclusive scan of g_degi (32768) -> g_base, single block of 1024
__global__ void scan_kernel(const int* __restrict__ deg, int* __restrict__ base) {
    __shared__ int part[1024];
    int t = threadIdx.x;
    int s = 0;
#pragma unroll
    for (int i = 0; i < 32; i++) s += deg[t * 32 + i];
    part[t] = s;
    __syncthreads();
    for (int off = 1; off < 1024; off <<= 1) {
        int v = (t >= off) ? part[t - off] : 0;
        __syncthreads();
        part[t] += v;
        __syncthreads();
    }
    int run = (t == 0) ? 0 : part[t - 1];
#pragma unroll
    for (int i = 0; i < 32; i++) {
        base[t * 32 + i] = run;
        run += deg[t * 32 + i];
    }
    if (t == 1023) base[NTOT] = run;
}

__global__ void fill_kernel(const int* __restrict__ dst, const int* __restrict__ base,
                            int* __restrict__ cursor, int* __restrict__ elist) {
    int e = blockIdx.x * blockDim.x + threadIdx.x;
    if (e < EDG) {
        int d = dst[e];
        int pos = base[d] + atomicAdd(&cursor[d], 1);
        elist[pos] = e;
    }
}

__global__ void sort_kernel(const int* __restrict__ base, int* __restrict__ elist) {
    int n = blockIdx.x * blockDim.x + threadIdx.x;
    if (n >= NTOT) return;
    int lo = base[n], hi = base[n + 1];
    for (int i = lo + 1; i < hi; i++) {
        int key = elist[i];
        int j = i - 1;
        while (j >= lo && elist[j] > key) { elist[j + 1] = elist[j]; j--; }
        elist[j + 1] = key;
    }
}

// ---------------- fused KNN + graph-feature kernel ----------------
// Round-14 PASSING kernel (2 queries/warp, TILE=128, cp.async double-buffered
// staging, per-lane 20-deep register lists, strict-< insertion in ascending
// candidate-index order, warp argmin merge tie->lower index, output-neutral
// tau gate) with ONE change: the d2 inner loop uses packed f32x2 sub/fma
// (Blackwell FFMA2), halving FMA-pipe instructions. Each packed lane is RN-
// rounded exactly like the scalar op, same accumulation order -> output
// bit-identical. qrow is staged pre-duplicated ({r,r} pairs) so one LDS.64
// yields the packed splat.
template <int C>
__global__ __launch_bounds__(256, 2) void knn_feat_kernel(const float* __restrict__ Xf,
                                                          float* __restrict__ F) {
    const int TILE = 128, WARPS = 8, STRIDE = 132, QPW = 2, QPB = WARPS * QPW;
    const int NT = QB / TILE;
    int b = blockIdx.y;
    int warp = threadIdx.x >> 5;
    int lane = threadIdx.x & 31;
    int qbase = blockIdx.x * QPB;
    const float* Xb = Xf + (size_t)b * C * QB;

    extern __shared__ float smem_dyn[];
    float* tbuf[2] = {smem_dyn, smem_dyn + C * STRIDE};   // two tile buffers
    float2* qrow2 = (float2*)(smem_dyn + 2 * C * STRIDE); // C*QPB float2 ({r,r})
    int* ssel = (int*)(qrow2 + C * QPB);                  // [WARPS*QPW*KNN]

    for (int i = threadIdx.x; i < C * QPB; i += 256) {
        float v = Xb[(i / QPB) * QB + qbase + (i % QPB)];
        qrow2[i] = make_float2(v, v);
    }

    int ql0 = warp * QPW;

    float val[QPW][KNN];
    int idx[QPW][KNN];
#pragma unroll
    for (int q = 0; q < QPW; q++)
#pragma unroll
        for (int p = 0; p < KNN; p++) { val[q][p] = INFINITY; idx[q][p] = 0x7fffffff; }
    float tau[QPW] = {INFINITY, INFINITY};

    // prefetch tile 0
    for (int ch = warp; ch < C; ch += WARPS)
        cp_async16(&tbuf[0][ch * STRIDE + lane * 4], Xb + ch * QB + lane * 4);
    cp_async_commit();
    cp_async_wait0();
    __syncthreads();

    for (int tt = 0; tt < NT; tt++) {
        const float* tile = tbuf[tt & 1];
        // prefetch next tile into the other buffer (overlapped with compute)
        if (tt + 1 < NT) {
            float* nbuf = tbuf[(tt + 1) & 1];
            int tn = (tt + 1) * TILE;
            for (int ch = warp; ch < C; ch += WARPS)
                cp_async16(&nbuf[ch * STRIDE + lane * 4], Xb + ch * QB + tn + lane * 4);
            cp_async_commit();
        }

        // packed accumulators: acc01/acc23 per query (pairs of fp32 lanes)
        uint64_t a01[QPW] = {0, 0}, a23[QPW] = {0, 0};

#pragma unroll
        for (int ch = 0; ch < C; ch++) {
            ulonglong2 c = *reinterpret_cast<const ulonglong2*>(&tile[ch * STRIDE + lane * 4]);
#pragma unroll
            for (int q = 0; q < QPW; q++) {
                uint64_t rr = *reinterpret_cast<const uint64_t*>(&qrow2[ch * QPB + ql0 + q]);
                uint64_t d01 = sub2(rr, c.x);
                uint64_t d23 = sub2(rr, c.y);
                a01[q] = fma2(d01, d01, a01[q]);
                a23[q] = fma2(d23, d23, a23[q]);
            }
        }

        int j0 = tt * TILE + lane * 4;
#pragma unroll
        for (int q = 0; q < QPW; q++) {
            float acc[4];
            unpack2(a01[q], acc[0], acc[1]);
            unpack2(a23[q], acc[2], acc[3]);
#pragma unroll
            for (int qq = 0; qq < 4; qq++) {
                float d2v = acc[qq];
                // tau gate (output-neutral) + lane list gate; strict <: ties lose
                if (d2v <= tau[q] && d2v < val[q][KNN - 1]) {
                    float cv = d2v;
                    int ci = j0 + qq;
#pragma unroll
                    for (int p = 0; p < KNN; p++) {
                        if (cv < val[q][p]) {
                            float tv = val[q][p]; val[q][p] = cv; cv = tv;
                            int ti = idx[q][p]; idx[q][p] = ci; ci = ti;
                        }
                    }
                }
            }
            // tau_q = warp-min of per-lane 20th (safe bound on final 20th)
            float t = val[q][KNN - 1];
#pragma unroll
            for (int off = 16; off; off >>= 1)
                t = fminf(t, __shfl_xor_sync(0xffffffffu, t, off));
            tau[q] = t;
        }

        if (tt + 1 < NT) {
            cp_async_wait0();
            __syncthreads();
        }
    }

    // exact smallest-20 across warp per query: argmin rounds, tie -> lower idx
#pragma unroll
    for (int q = 0; q < QPW; q++) {
        for (int r = 0; r < KNN; r++) {
            float cv = val[q][0];
            int ci = idx[q][0];
#pragma unroll
            for (int off = 16; off; off >>= 1) {
                float ov = __shfl_xor_sync(0xffffffffu, cv, off);
                int oi = __shfl_xor_sync(0xffffffffu, ci, off);
                if (ov < cv || (ov == cv && oi < ci)) { cv = ov; ci = oi; }
            }
            if (ci == idx[q][0]) {
#pragma unroll
                for (int p = 0; p < KNN - 1; p++) {
                    val[q][p] = val[q][p + 1];
                    idx[q][p] = idx[q][p + 1];
                }
                val[q][KNN - 1] = INFINITY;
                idx[q][KNN - 1] = 0x7fffffff;
            }
            if (lane == 0) ssel[(warp * QPW + q) * KNN + r] = ci;
        }
    }
    __syncwarp();

    // graph feature (full fp32): F[:C] = max_k(nbr-ctr), F[C:2C] = ctr
#pragma unroll
    for (int q = 0; q < QPW; q++) {
        int qg = ql0 + q;
        int iq = qbase + qg;
        int nb[KNN];
#pragma unroll
        for (int r = 0; r < KNN; r++) nb[r] = ssel[(warp * QPW + q) * KNN + r];
        size_t ob = (size_t)(b * QB + iq) * (2 * C);
#pragma unroll
        for (int s = 0; s < (C + 31) / 32; s++) {
            int ch = lane + 32 * s;
            if (ch < C) {
                float ctr = qrow2[ch * QPB + qg].x;
                float mx = -INFINITY;
#pragma unroll
                for (int r = 0; r < KNN; r++)
                    mx = fmaxf(mx, __fadd_rn(Xb[ch * QB + nb[r]], -ctr));
                F[ob + ch] = mx;
                F[ob + C + ch] = ctr;
            }
        }
    }
}

// ---------------- graph conv pieces ----------------
template <int CH>
__global__ void scale_kernel(const float* __restrict__ F, const float* __restrict__ ns,
                             float* __restrict__ m) {
    int i = blockIdx.x * blockDim.x + threadIdx.x;
    if (i < NTOT * CH) {
        int node = i / CH;
        m[i] = __fmul_rn(F[i], ns[node]);
    }
}

// deterministic segment_sum: ascending edge-id order per node
template <int CH>
__global__ void gather_sum_kernel(const int* __restrict__ srcArr,
                                  const int* __restrict__ base,
                                  const int* __restrict__ elist,
                                  const float* __restrict__ m,
                                  float* __restrict__ agg) {
    int i = blockIdx.x * blockDim.x + threadIdx.x;
    if (i >= NTOT * CH) return;
    int node = i / CH;
    int c = i % CH;
    int lo = base[node], hi = base[node + 1];
    float acc = 0.f;
    for (int k = lo; k < hi; k++) {
        int s = srcArr[elist[k]];
        acc = __fadd_rn(acc, m[(size_t)s * CH + c]);
    }
    agg[i] = acc;
}

// out = relu?((agg*nd) @ W + b) ; fp32 FMA, nd-scale BEFORE gemm
template <int IN, int OUT, bool RELU>
__global__ void conv_gemm_kernel(const float* __restrict__ agg, const float* __restrict__ nd,
                                 const float* __restrict__ W, const float* __restrict__ bias,
                                 float* __restrict__ out) {
    constexpr int NPB = 256 / OUT;
    __shared__ float srow[NPB][IN];
    int node0 = blockIdx.x * NPB;
    for (int l = threadIdx.x; l < NPB * IN; l += 256) {
        int nn = l / IN, ch = l % IN;
        srow[nn][ch] = __fmul_rn(agg[(size_t)(node0 + nn) * IN + ch], nd[node0 + nn]);
    }
    __syncthreads();
    int nl = threadIdx.x / OUT;
    int o = threadIdx.x % OUT;
    int node = node0 + nl;
    float acc = 0.f;
#pragma unroll
    for (int ch = 0; ch < IN; ch++) acc = __fmaf_rn(srow[nl][ch], W[ch * OUT + o], acc);
    acc = __fadd_rn(acc, bias[o]);
    if (RELU) acc = fmaxf(acc, 0.f);
    out[(size_t)node * OUT + o] = acc;
}

// ---------------- launch ----------------
extern "C" void kernel_launch(void* const* d_in, const int* in_sizes, int n_in,
                              void* d_out, int out_size) {
    const float* feats = (const float*)d_in[0];
    const int* src = (const int*)d_in[1];
    const int* dst = (const int*)d_in[2];
    const float* W1 = (const float*)d_in[3];
    const float* b1 = (const float*)d_in[4];
    const float* W2 = (const float*)d_in[5];
    const float* b2 = (const float*)d_in[6];
    const float* W3 = (const float*)d_in[7];
    const float* b3 = (const float*)d_in[8];
    float* out = (float*)d_out;

    float *f, *m, *agg, *h1, *h2, *ns, *nd;
    int *degi, *base, *cursor, *elist;
    cudaGetSymbolAddress((void**)&f, g_f);
    cudaGetSymbolAddress((void**)&m, g_m);
    cudaGetSymbolAddress((void**)&agg, g_agg);
    cudaGetSymbolAddress((void**)&h1, g_h1);
    cudaGetSymbolAddress((void**)&h2, g_h2);
    cudaGetSymbolAddress((void**)&ns, g_ns);
    cudaGetSymbolAddress((void**)&nd, g_nd);
    cudaGetSymbolAddress((void**)&degi, g_degi);
    cudaGetSymbolAddress((void**)&base, g_base);
    cudaGetSymbolAddress((void**)&cursor, g_cursor);
    cudaGetSymbolAddress((void**)&elist, g_elist);

    const int T = 256;

    // dynamic smem: 2 tile buffers + duplicated qrow (float2) + ssel
    const int smem3 = (2 * 3 * 132 + 3 * 16 * 2) * 4 + 8 * 2 * KNN * 4;
    const int smem64 = (2 * 64 * 132 + 64 * 16 * 2) * 4 + 8 * 2 * KNN * 4;
    cudaFuncSetAttribute(knn_feat_kernel<3>,
                         cudaFuncAttributeMaxDynamicSharedMemorySize, smem3);
    cudaFuncSetAttribute(knn_feat_kernel<64>,
                         cudaFuncAttributeMaxDynamicSharedMemorySize, smem64);

    zero_f_kernel<<<NTOT / T, T>>>(ns, NTOT);
    zero_f_kernel<<<NTOT / T, T>>>(nd, NTOT);
    zero_i_kernel<<<NTOT / T, T>>>(degi, NTOT);
    zero_i_kernel<<<NTOT / T, T>>>(cursor, NTOT);
    deg_kernel<<<EDG / T, T>>>(src, dst, ns, nd, degi);
    norm_kernel<<<NTOT / T, T>>>(ns, NTOT);
    norm_kernel<<<NTOT / T, T>>>(nd, NTOT);

    scan_kernel<<<1, 1024>>>(degi, base);
    fill_kernel<<<EDG / T, T>>>(dst, base, cursor, elist);
    sort_kernel<<<NTOT / T, T>>>(base, elist);

    // ---- layer 1 (c=3) ----
    knn_feat_kernel<3><<<dim3(QB / 16, NBATCH), 256, smem3>>>(feats, f);
    scale_kernel<6><<<(NTOT * 6 + T - 1) / T, T>>>(f, ns, m);
    gather_sum_kernel<6><<<(NTOT * 6 + T - 1) / T, T>>>(src, base, elist, m, agg);
    conv_gemm_kernel<6, 64, true><<<NTOT / 4, 256>>>(agg, nd, W1, b1, h1);

    // ---- layer 2 (c=64) ----
    knn_feat_kernel<64><<<dim3(QB / 16, NBATCH), 256, smem64>>>(h1, f);
    scale_kernel<128><<<NTOT * 128 / T, T>>>(f, ns, m);
    gather_sum_kernel<128><<<NTOT * 128 / T, T>>>(src, base, elist, m, agg);
    conv_gemm_kernel<128, 64, true><<<NTOT / 4, 256>>>(agg, nd, W2, b2, h2);

    // ---- layer 3 (c=64) ----
    knn_feat_kernel<64><<<dim3(QB / 16, NBATCH), 256, smem64>>>(h2, f);
    scale_kernel<128><<<NTOT * 128 / T, T>>>(f, ns, m);
    gather_sum_kernel<128><<<NTOT * 128 / T, T>>>(src, base, elist, m, agg);
    conv_gemm_kernel<128, 8, false><<<NTOT / 32, 256>>>(agg, nd, W3, b3, out);
}

// round 16
// speedup vs baseline: 1.0522x; 1.0522x over previous
#include <cuda_runtime.h>
#include <math.h>
#include <stdint.h>

#define NTOT 32768
#define QB   8192
#define NBATCH 4
#define EDG  524288
#define KNN  20

// ---------------- cp.async helpers ----------------
__device__ __forceinline__ void cp_async16(void* smem_dst, const void* gmem_src) {
    uint32_t d = (uint32_t)__cvta_generic_to_shared(smem_dst);
    asm volatile("cp.async.cg.shared.global [%0], [%1], 16;" :: "r"(d), "l"(gmem_src));
}
__device__ __forceinline__ void cp_async_commit() {
    asm volatile("cp.async.commit_group;");
}
__device__ __forceinline__ void cp_async_wait0() {
    asm volatile("cp.async.wait_group 0;");
}

// ---------------- scratch (static device globals; no allocation) ----------------
__device__ __align__(16) float g_f[NTOT * 128];    // pooled edge features
__device__ __align__(16) float g_agg[NTOT * 128];  // segment-sum result
__device__ __align__(16) float g_h1[NTOT * 64];
__device__ __align__(16) float g_h2[NTOT * 64];
__device__ float g_ns[NTOT];
__device__ float g_nd[NTOT];
// CSR over dst (edge ids ascending per node)
__device__ int g_degi[NTOT];
__device__ int g_base[NTOT + 1];
__device__ int g_cursor[NTOT];
__device__ int g_elist[EDG];

// ---------------- small utility kernels ----------------
__global__ void zero_f_kernel(float* __restrict__ p, int n) {
    int i = blockIdx.x * blockDim.x + threadIdx.x;
    if (i < n) p[i] = 0.f;
}
__global__ void zero_i_kernel(int* __restrict__ p, int n) {
    int i = blockIdx.x * blockDim.x + threadIdx.x;
    if (i < n) p[i] = 0;
}

__global__ void deg_kernel(const int* __restrict__ src, const int* __restrict__ dst,
                           float* __restrict__ dego, float* __restrict__ degi,
                           int* __restrict__ degi_i) {
    int e = blockIdx.x * blockDim.x + threadIdx.x;
    if (e < EDG) {
        atomicAdd(&dego[src[e]], 1.f);
        atomicAdd(&degi[dst[e]], 1.f);
        atomicAdd(&degi_i[dst[e]], 1);
    }
}

__global__ void norm_kernel(float* __restrict__ a, int n) {
    int i = blockIdx.x * blockDim.x + threadIdx.x;
    if (i < n) {
        float d = a[i];
        a[i] = (d > 0.f) ? (float)(1.0 / sqrt((double)fmaxf(d, 1.f))) : 0.f;
    }
}

// exclusive scan of g_degi (32768) -> g_base, single block of 1024
__global__ void scan_kernel(const int* __restrict__ deg, int* __restrict__ base) {
    __shared__ int part[1024];
    int t = threadIdx.x;
    int s = 0;
#pragma unroll
    for (int i = 0; i < 32; i++) s += deg[t * 32 + i];
    part[t] = s;
    __syncthreads();
    for (int off = 1; off < 1024; off <<= 1) {
        int v = (t >= off) ? part[t - off] : 0;
        __syncthreads();
        part[t] += v;
        __syncthreads();
    }
    int run = (t == 0) ? 0 : part[t - 1];
#pragma unroll
    for (int i = 0; i < 32; i++) {
        base[t * 32 + i] = run;
        run += deg[t * 32 + i];
    }
    if (t == 1023) base[NTOT] = run;
}

__global__ void fill_kernel(const int* __restrict__ dst, const int* __restrict__ base,
                            int* __restrict__ cursor, int* __restrict__ elist) {
    int e = blockIdx.x * blockDim.x + threadIdx.x;
    if (e < EDG) {
        int d = dst[e];
        int pos = base[d] + atomicAdd(&cursor[d], 1);
        elist[pos] = e;
    }
}

__global__ void sort_kernel(const int* __restrict__ base, int* __restrict__ elist) {
    int n = blockIdx.x * blockDim.x + threadIdx.x;
    if (n >= NTOT) return;
    int lo = base[n], hi = base[n + 1];
    for (int i = lo + 1; i < hi; i++) {
        int key = elist[i];
        int j = i - 1;
        while (j >= lo && elist[j] > key) { elist[j + 1] = elist[j]; j--; }
        elist[j + 1] = key;
    }
}

// ---------------- fused KNN + graph-feature kernel ----------------
// Round-14 PASSING kernel (2 queries/warp, TILE=128, cp.async double-buffered
// staging, per-lane 20-deep register lists, strict-< insertion in ascending
// candidate-index order, warp argmin merge tie->lower index, output-neutral
// tau gate) with two output-neutral micro-opts:
//  - both query values per (ch,warp) loaded with ONE float2 LDS.64 (ql0 even)
//  - tau refreshed every 2nd tile (stale tau >= current tau >= final 20th, so
//    it only over-admits; live admission still uses strict < vs val[q][19])
template <int C>
__global__ __launch_bounds__(256, 2) void knn_feat_kernel(const float* __restrict__ Xf,
                                                          float* __restrict__ F) {
    const int TILE = 128, WARPS = 8, STRIDE = 132, QPW = 2, QPB = WARPS * QPW;
    const int NT = QB / TILE;
    int b = blockIdx.y;
    int warp = threadIdx.x >> 5;
    int lane = threadIdx.x & 31;
    int qbase = blockIdx.x * QPB;
    const float* Xb = Xf + (size_t)b * C * QB;

    extern __shared__ float smem_dyn[];
    float* tbuf[2] = {smem_dyn, smem_dyn + C * STRIDE};  // two tile buffers
    float* qrow = smem_dyn + 2 * C * STRIDE;             // C*QPB, ch-major
    int* ssel = (int*)(qrow + C * QPB);                  // [WARPS*QPW*KNN]

    for (int i = threadIdx.x; i < C * QPB; i += 256)
        qrow[i] = Xb[(i / QPB) * QB + qbase + (i % QPB)];

    int ql0 = warp * QPW;  // even

    float val[QPW][KNN];
    int idx[QPW][KNN];
#pragma unroll
    for (int q = 0; q < QPW; q++)
#pragma unroll
        for (int p = 0; p < KNN; p++) { val[q][p] = INFINITY; idx[q][p] = 0x7fffffff; }
    float tau[QPW] = {INFINITY, INFINITY};

    // prefetch tile 0
    for (int ch = warp; ch < C; ch += WARPS)
        cp_async16(&tbuf[0][ch * STRIDE + lane * 4], Xb + ch * QB + lane * 4);
    cp_async_commit();
    cp_async_wait0();
    __syncthreads();

    for (int tt = 0; tt < NT; tt++) {
        const float* tile = tbuf[tt & 1];
        // prefetch next tile into the other buffer (overlapped with compute)
        if (tt + 1 < NT) {
            float* nbuf = tbuf[(tt + 1) & 1];
            int tn = (tt + 1) * TILE;
            for (int ch = warp; ch < C; ch += WARPS)
                cp_async16(&nbuf[ch * STRIDE + lane * 4], Xb + ch * QB + tn + lane * 4);
            cp_async_commit();
        }

        float acc[QPW][4];
#pragma unroll
        for (int q = 0; q < QPW; q++)
#pragma unroll
            for (int s = 0; s < 4; s++) acc[q][s] = 0.f;

#pragma unroll
        for (int ch = 0; ch < C; ch++) {
            float4 c4 = *reinterpret_cast<const float4*>(&tile[ch * STRIDE + lane * 4]);
            float2 r2 = *reinterpret_cast<const float2*>(&qrow[ch * QPB + ql0]);
            float rv[QPW] = {r2.x, r2.y};
#pragma unroll
            for (int q = 0; q < QPW; q++) {
                float r = rv[q];
                float d0 = r - c4.x;
                float d1 = r - c4.y;
                float d2 = r - c4.z;
                float d3 = r - c4.w;
                acc[q][0] = __fmaf_rn(d0, d0, acc[q][0]);
                acc[q][1] = __fmaf_rn(d1, d1, acc[q][1]);
                acc[q][2] = __fmaf_rn(d2, d2, acc[q][2]);
                acc[q][3] = __fmaf_rn(d3, d3, acc[q][3]);
            }
        }

        int j0 = tt * TILE + lane * 4;
#pragma unroll
        for (int q = 0; q < QPW; q++) {
#pragma unroll
            for (int qq = 0; qq < 4; qq++) {
                float d2v = acc[q][qq];
                // tau gate (output-neutral) + lane list gate; strict <: ties lose
                if (d2v <= tau[q] && d2v < val[q][KNN - 1]) {
                    float cv = d2v;
                    int ci = j0 + qq;
#pragma unroll
                    for (int p = 0; p < KNN; p++) {
                        if (cv < val[q][p]) {
                            float tv = val[q][p]; val[q][p] = cv; cv = tv;
                            int ti = idx[q][p]; idx[q][p] = ci; ci = ti;
                        }
                    }
                }
            }
        }
        // tau refresh every 2nd tile (stale tau is a safe over-estimate)
        if (tt & 1) {
#pragma unroll
            for (int q = 0; q < QPW; q++) {
                float t = val[q][KNN - 1];
#pragma unroll
                for (int off = 16; off; off >>= 1)
                    t = fminf(t, __shfl_xor_sync(0xffffffffu, t, off));
                tau[q] = t;
            }
        }

        if (tt + 1 < NT) {
            cp_async_wait0();
            __syncthreads();
        }
    }

    // exact smallest-20 across warp per query: argmin rounds, tie -> lower idx
#pragma unroll
    for (int q = 0; q < QPW; q++) {
        for (int r = 0; r < KNN; r++) {
            float cv = val[q][0];
            int ci = idx[q][0];
#pragma unroll
            for (int off = 16; off; off >>= 1) {
                float ov = __shfl_xor_sync(0xffffffffu, cv, off);
                int oi = __shfl_xor_sync(0xffffffffu, ci, off);
                if (ov < cv || (ov == cv && oi < ci)) { cv = ov; ci = oi; }
            }
            if (ci == idx[q][0]) {
#pragma unroll
                for (int p = 0; p < KNN - 1; p++) {
                    val[q][p] = val[q][p + 1];
                    idx[q][p] = idx[q][p + 1];
                }
                val[q][KNN - 1] = INFINITY;
                idx[q][KNN - 1] = 0x7fffffff;
            }
            if (lane == 0) ssel[(warp * QPW + q) * KNN + r] = ci;
        }
    }
    __syncwarp();

    // graph feature (full fp32): F[:C] = max_k(nbr-ctr), F[C:2C] = ctr
#pragma unroll
    for (int q = 0; q < QPW; q++) {
        int qg = ql0 + q;
        int iq = qbase + qg;
        int nb[KNN];
#pragma unroll
        for (int r = 0; r < KNN; r++) nb[r] = ssel[(warp * QPW + q) * KNN + r];
        size_t ob = (size_t)(b * QB + iq) * (2 * C);
#pragma unroll
        for (int s = 0; s < (C + 31) / 32; s++) {
            int ch = lane + 32 * s;
            if (ch < C) {
                float ctr = qrow[ch * QPB + qg];
                float mx = -INFINITY;
#pragma unroll
                for (int r = 0; r < KNN; r++)
                    mx = fmaxf(mx, __fadd_rn(Xb[ch * QB + nb[r]], -ctr));
                F[ob + ch] = mx;
                F[ob + C + ch] = ctr;
            }
        }
    }
}

// ---------------- graph conv pieces ----------------
// deterministic segment_sum with fused ns-scaling: per (node, channel),
// sequential adds in ascending edge-id order of rn(F[s][c] * ns[s]) — value-
// identical to the previous scale-then-gather two-pass.
template <int CH>
__global__ void gather_sum_kernel(const int* __restrict__ srcArr,
                                  const int* __restrict__ base,
                                  const int* __restrict__ elist,
                                  const float* __restrict__ Fm,
                                  const float* __restrict__ ns,
                                  float* __restrict__ agg) {
    int i = blockIdx.x * blockDim.x + threadIdx.x;
    if (i >= NTOT * CH) return;
    int node = i / CH;
    int c = i % CH;
    int lo = base[node], hi = base[node + 1];
    float acc = 0.f;
    for (int k = lo; k < hi; k++) {
        int s = srcArr[elist[k]];
        acc = __fadd_rn(acc, __fmul_rn(Fm[(size_t)s * CH + c], ns[s]));
    }
    agg[i] = acc;
}

// out = relu?((agg*nd) @ W + b) ; fp32 FMA, nd-scale BEFORE gemm
template <int IN, int OUT, bool RELU>
__global__ void conv_gemm_kernel(const float* __restrict__ agg, const float* __restrict__ nd,
                                 const float* __restrict__ W, const float* __restrict__ bias,
                                 float* __restrict__ out) {
    constexpr int NPB = 256 / OUT;
    __shared__ float srow[NPB][IN];
    int node0 = blockIdx.x * NPB;
    for (int l = threadIdx.x; l < NPB * IN; l += 256) {
        int nn = l / IN, ch = l % IN;
        srow[nn][ch] = __fmul_rn(agg[(size_t)(node0 + nn) * IN + ch], nd[node0 + nn]);
    }
    __syncthreads();
    int nl = threadIdx.x / OUT;
    int o = threadIdx.x % OUT;
    int node = node0 + nl;
    float acc = 0.f;
#pragma unroll
    for (int ch = 0; ch < IN; ch++) acc = __fmaf_rn(srow[nl][ch], W[ch * OUT + o], acc);
    acc = __fadd_rn(acc, bias[o]);
    if (RELU) acc = fmaxf(acc, 0.f);
    out[(size_t)node * OUT + o] = acc;
}

// ---------------- launch ----------------
extern "C" void kernel_launch(void* const* d_in, const int* in_sizes, int n_in,
                              void* d_out, int out_size) {
    const float* feats = (const float*)d_in[0];
    const int* src = (const int*)d_in[1];
    const int* dst = (const int*)d_in[2];
    const float* W1 = (const float*)d_in[3];
    const float* b1 = (const float*)d_in[4];
    const float* W2 = (const float*)d_in[5];
    const float* b2 = (const float*)d_in[6];
    const float* W3 = (const float*)d_in[7];
    const float* b3 = (const float*)d_in[8];
    float* out = (float*)d_out;

    float *f, *agg, *h1, *h2, *ns, *nd;
    int *degi, *base, *cursor, *elist;
    cudaGetSymbolAddress((void**)&f, g_f);
    cudaGetSymbolAddress((void**)&agg, g_agg);
    cudaGetSymbolAddress((void**)&h1, g_h1);
    cudaGetSymbolAddress((void**)&h2, g_h2);
    cudaGetSymbolAddress((void**)&ns, g_ns);
    cudaGetSymbolAddress((void**)&nd, g_nd);
    cudaGetSymbolAddress((void**)&degi, g_degi);
    cudaGetSymbolAddress((void**)&base, g_base);
    cudaGetSymbolAddress((void**)&cursor, g_cursor);
    cudaGetSymbolAddress((void**)&elist, g_elist);

    const int T = 256;

    // dynamic smem: 2 tile buffers + qrow + ssel
    const int smem3 = (2 * 3 * 132 + 3 * 16) * 4 + 8 * 2 * KNN * 4;
    const int smem64 = (2 * 64 * 132 + 64 * 16) * 4 + 8 * 2 * KNN * 4;
    cudaFuncSetAttribute(knn_feat_kernel<3>,
                         cudaFuncAttributeMaxDynamicSharedMemorySize, smem3);
    cudaFuncSetAttribute(knn_feat_kernel<64>,
                         cudaFuncAttributeMaxDynamicSharedMemorySize, smem64);

    zero_f_kernel<<<NTOT / T, T>>>(ns, NTOT);
    zero_f_kernel<<<NTOT / T, T>>>(nd, NTOT);
    zero_i_kernel<<<NTOT / T, T>>>(degi, NTOT);
    zero_i_kernel<<<NTOT / T, T>>>(cursor, NTOT);
    deg_kernel<<<EDG / T, T>>>(src, dst, ns, nd, degi);
    norm_kernel<<<NTOT / T, T>>>(ns, NTOT);
    norm_kernel<<<NTOT / T, T>>>(nd, NTOT);

    scan_kernel<<<1, 1024>>>(degi, base);
    fill_kernel<<<EDG / T, T>>>(dst, base, cursor, elist);
    sort_kernel<<<NTOT / T, T>>>(base, elist);

    // ---- layer 1 (c=3) ----
    knn_feat_kernel<3><<<dim3(QB / 16, NBATCH), 256, smem3>>>(feats, f);
    gather_sum_kernel<6><<<(NTOT * 6 + T - 1) / T, T>>>(src, base, elist, f, ns, agg);
    conv_gemm_kernel<6, 64, true><<<NTOT / 4, 256>>>(agg, nd, W1, b1, h1);

    // ---- layer 2 (c=64) ----
    knn_feat_kernel<64><<<dim3(QB / 16, NBATCH), 256, smem64>>>(h1, f);
    gather_sum_kernel<128><<<NTOT * 128 / T, T>>>(src, base, elist, f, ns, agg);
    conv_gemm_kernel<128, 64, true><<<NTOT / 4, 256>>>(agg, nd, W2, b2, h2);

    // ---- layer 3 (c=64) ----
    knn_feat_kernel<64><<<dim3(QB / 16, NBATCH), 256, smem64>>>(h2, f);
    gather_sum_kernel<128><<<NTOT * 128 / T, T>>>(src, base, elist, f, ns, agg);
    conv_gemm_kernel<128, 8, false><<<NTOT / 32, 256>>>(agg, nd, W3, b3, out);
}